// round 1
// baseline (speedup 1.0000x reference)
#include <cuda_runtime.h>
#include <math.h>

// ---------------- problem constants ----------------
#define BB 4
#define SS 2048
#define DD 512
#define HH 8
#define DHEAD 64
#define DFF 2048
#define NTOK (BB*SS)          // 8192 tokens
#define NT (NTOK*DD)          // 4194304 floats per [tokens, 512] buffer

// ---------------- scratch (static device memory; no runtime allocs) ----------
// layout (units of NT floats):
//  0: Z   1: Q   2: K   3: V   4: QH  5: KH  6: VH  7: ATT  8: AO  9: A
//  10..13: H1 (8192 x 2048)   14: F
//  then 3 repacked weights of 512*512
__device__ float g_scratch[15*(size_t)NT + 3*DD*DD];

// ---------------- embedding + sinusoidal PE ----------------
__global__ void embed_pe_kernel(const int* __restrict__ x, const float* __restrict__ emb,
                                float* __restrict__ z)
{
    int idx = blockIdx.x * blockDim.x + threadIdx.x;
    if (idx >= NT) return;
    int d = idx & (DD - 1);
    int t = idx >> 9;            // global token
    int s = t & (SS - 1);        // position within sequence
    float di = (float)d * (1.0f / (float)DD);
    float ang = (float)s / powf(10000.0f, di);
    float pe = (d & 1) ? cosf(ang) : sinf(ang);
    z[idx] = emb[(size_t)x[t] * DD + d] + pe;
}

// ---------------- repack per-head weight [H,512,64] -> [512, H*64] ----------
__global__ void repack_kernel(const float* __restrict__ W, float* __restrict__ Wr)
{
    int idx = blockIdx.x * blockDim.x + threadIdx.x;
    if (idx >= DD * DD) return;
    int n = idx & (DD - 1);
    int d = idx >> 9;
    int h = n >> 6, k = n & 63;
    Wr[idx] = W[((size_t)h * DD + d) * DHEAD + k];
}

// ---------------- SGEMM: C[M,N] = A[M,K] @ W[K,N] + bias (+relu) -------------
// 128x128 tile, BK=16, 256 threads, 8x8 per thread
__global__ __launch_bounds__(256) void gemm_bias_kernel(
    int M, int N, int K,
    const float* __restrict__ A, const float* __restrict__ W,
    const float* __restrict__ bias, float* __restrict__ C, int relu)
{
    __shared__ float As[16][128];   // transposed A tile: As[k][m]
    __shared__ float Bs[16][128];

    const int tid = threadIdx.x;
    const int m0 = blockIdx.y * 128;
    const int n0 = blockIdx.x * 128;
    const int tx = tid & 15, ty = tid >> 4;

    float acc[8][8];
#pragma unroll
    for (int i = 0; i < 8; i++)
#pragma unroll
        for (int j = 0; j < 8; j++) acc[i][j] = 0.f;

    for (int k0 = 0; k0 < K; k0 += 16) {
#pragma unroll
        for (int p = 0; p < 2; p++) {
            int v = tid + p * 256;
            int row = v >> 2;
            int kc = (v & 3) * 4;
            float4 av = *(const float4*)&A[(size_t)(m0 + row) * K + k0 + kc];
            As[kc + 0][row] = av.x;
            As[kc + 1][row] = av.y;
            As[kc + 2][row] = av.z;
            As[kc + 3][row] = av.w;
        }
#pragma unroll
        for (int p = 0; p < 2; p++) {
            int v = tid + p * 256;
            int br = v >> 5;
            int bc = (v & 31) * 4;
            *(float4*)&Bs[br][bc] = *(const float4*)&W[(size_t)(k0 + br) * N + n0 + bc];
        }
        __syncthreads();
#pragma unroll
        for (int kk = 0; kk < 16; kk++) {
            float ra[8], rb[8];
            *(float4*)&ra[0] = *(const float4*)&As[kk][ty * 8];
            *(float4*)&ra[4] = *(const float4*)&As[kk][ty * 8 + 4];
            *(float4*)&rb[0] = *(const float4*)&Bs[kk][tx * 8];
            *(float4*)&rb[4] = *(const float4*)&Bs[kk][tx * 8 + 4];
#pragma unroll
            for (int i = 0; i < 8; i++)
#pragma unroll
                for (int j = 0; j < 8; j++)
                    acc[i][j] += ra[i] * rb[j];
        }
        __syncthreads();
    }

#pragma unroll
    for (int i = 0; i < 8; i++) {
        int row = m0 + ty * 8 + i;
#pragma unroll
        for (int j0 = 0; j0 < 8; j0 += 4) {
            float4 bv = *(const float4*)&bias[n0 + tx * 8 + j0];
            float4 cv;
            cv.x = acc[i][j0 + 0] + bv.x;
            cv.y = acc[i][j0 + 1] + bv.y;
            cv.z = acc[i][j0 + 2] + bv.z;
            cv.w = acc[i][j0 + 3] + bv.w;
            if (relu) {
                cv.x = fmaxf(cv.x, 0.f); cv.y = fmaxf(cv.y, 0.f);
                cv.z = fmaxf(cv.z, 0.f); cv.w = fmaxf(cv.w, 0.f);
            }
            *(float4*)&C[(size_t)row * N + n0 + tx * 8 + j0] = cv;
        }
    }
}

// ---------------- flash attention (non-causal, fp32) -------------------------
// Q/K/V layout: [token, h*64+k] (i.e. [8192, 512]). One CTA = 64 q rows of one
// (b,h). Online softmax, P tile staged through smem.
#define ASTR 68
#define ATT_SMEM (4 * 64 * ASTR * (int)sizeof(float))

__global__ __launch_bounds__(256) void attention_kernel(
    const float* __restrict__ Qh, const float* __restrict__ Kh,
    const float* __restrict__ Vh, float* __restrict__ Out)
{
    extern __shared__ float sm[];
    float* Qt = sm;                 // [k][r]  (pre-scaled by 1/8)
    float* Kt = Qt + 64 * ASTR;     // [k][c]
    float* Vs = Kt + 64 * ASTR;     // [s][v]
    float* Ps = Vs + 64 * ASTR;     // [r][s]

    const int tid = threadIdx.x;
    const int tx = tid & 15, ty = tid >> 4;
    const int q0 = blockIdx.x * 64;
    const int bh = blockIdx.y;
    const int rb = (bh >> 3) * SS;      // token row base for this batch
    const int cq = (bh & 7) * DHEAD;    // column offset of this head

#pragma unroll
    for (int it = 0; it < 16; ++it) {
        int idx = it * 256 + tid;
        int r = idx >> 6, k = idx & 63;
        Qt[k * ASTR + r] = Qh[(size_t)(rb + q0 + r) * DD + cq + k] * 0.125f;
    }

    float m[4], l[4], o[4][4];
#pragma unroll
    for (int i = 0; i < 4; i++) {
        m[i] = -1e30f; l[i] = 0.f;
#pragma unroll
        for (int j = 0; j < 4; j++) o[i][j] = 0.f;
    }

    for (int s0 = 0; s0 < SS; s0 += 64) {
        __syncthreads();   // prior PV reads done (and Q store visible on iter 0)
#pragma unroll
        for (int it = 0; it < 16; ++it) {
            int idx = it * 256 + tid;
            int r = idx >> 6, k = idx & 63;
            Kt[k * ASTR + r] = Kh[(size_t)(rb + s0 + r) * DD + cq + k];
            Vs[r * ASTR + k] = Vh[(size_t)(rb + s0 + r) * DD + cq + k];
        }
        __syncthreads();

        float sc[4][4];
#pragma unroll
        for (int i = 0; i < 4; i++)
#pragma unroll
            for (int j = 0; j < 4; j++) sc[i][j] = 0.f;

        for (int k = 0; k < 64; k++) {
            float4 qa = *(const float4*)&Qt[k * ASTR + ty * 4];
            float4 kb = *(const float4*)&Kt[k * ASTR + tx * 4];
            float ra[4] = { qa.x, qa.y, qa.z, qa.w };
            float rk[4] = { kb.x, kb.y, kb.z, kb.w };
#pragma unroll
            for (int i = 0; i < 4; i++)
#pragma unroll
                for (int j = 0; j < 4; j++)
                    sc[i][j] += ra[i] * rk[j];
        }

        // online softmax per score row (reduce across the 16 tx lanes)
#pragma unroll
        for (int i = 0; i < 4; i++) {
            float rm = fmaxf(fmaxf(sc[i][0], sc[i][1]), fmaxf(sc[i][2], sc[i][3]));
#pragma unroll
            for (int off = 1; off < 16; off <<= 1)
                rm = fmaxf(rm, __shfl_xor_sync(0xffffffffu, rm, off));
            float mn = fmaxf(m[i], rm);
            float alpha = __expf(m[i] - mn);
            float rs = 0.f;
#pragma unroll
            for (int j = 0; j < 4; j++) {
                float p = __expf(sc[i][j] - mn);
                sc[i][j] = p;
                rs += p;
            }
#pragma unroll
            for (int off = 1; off < 16; off <<= 1)
                rs += __shfl_xor_sync(0xffffffffu, rs, off);
            l[i] = l[i] * alpha + rs;
            m[i] = mn;
#pragma unroll
            for (int j = 0; j < 4; j++) o[i][j] *= alpha;
        }

#pragma unroll
        for (int i = 0; i < 4; i++)
#pragma unroll
            for (int j = 0; j < 4; j++)
                Ps[(ty * 4 + i) * ASTR + tx * 4 + j] = sc[i][j];
        __syncthreads();

        for (int s = 0; s < 64; s++) {
            float4 vb = *(const float4*)&Vs[s * ASTR + tx * 4];
            float rv[4] = { vb.x, vb.y, vb.z, vb.w };
            float rp[4];
#pragma unroll
            for (int i = 0; i < 4; i++) rp[i] = Ps[(ty * 4 + i) * ASTR + s];
#pragma unroll
            for (int i = 0; i < 4; i++)
#pragma unroll
                for (int j = 0; j < 4; j++)
                    o[i][j] += rp[i] * rv[j];
        }
    }

#pragma unroll
    for (int i = 0; i < 4; i++) {
        float inv = 1.f / l[i];
#pragma unroll
        for (int j = 0; j < 4; j++)
            Out[(size_t)(rb + q0 + ty * 4 + i) * DD + cq + tx * 4 + j] = o[i][j] * inv;
    }
}

// ---------------- fused residual + LayerNorm (+relu) -------------------------
__global__ __launch_bounds__(128) void add_ln_kernel(
    const float* __restrict__ X, const float* __restrict__ R,
    const float* __restrict__ gamma, const float* __restrict__ beta,
    float* __restrict__ out, int relu)
{
    const int row = blockIdx.x;
    const int tid = threadIdx.x;

    float4 xv = *(const float4*)&X[(size_t)row * DD + tid * 4];
    float4 rv = *(const float4*)&R[(size_t)row * DD + tid * 4];
    float v[4] = { xv.x + rv.x, xv.y + rv.y, xv.z + rv.z, xv.w + rv.w };

    float s = v[0] + v[1] + v[2] + v[3];
    float sq = v[0] * v[0] + v[1] * v[1] + v[2] * v[2] + v[3] * v[3];
#pragma unroll
    for (int off = 16; off >= 1; off >>= 1) {
        s += __shfl_xor_sync(0xffffffffu, s, off);
        sq += __shfl_xor_sync(0xffffffffu, sq, off);
    }
    __shared__ float sw[4], sqw[4];
    int w = tid >> 5;
    if ((tid & 31) == 0) { sw[w] = s; sqw[w] = sq; }
    __syncthreads();
    s = sw[0] + sw[1] + sw[2] + sw[3];
    sq = sqw[0] + sqw[1] + sqw[2] + sqw[3];

    float mean = s * (1.0f / (float)DD);
    float var = sq * (1.0f / (float)DD) - mean * mean;
    float rstd = rsqrtf(var + 1e-5f);

    float4 gv = *(const float4*)&gamma[tid * 4];
    float4 bv = *(const float4*)&beta[tid * 4];
    float ga[4] = { gv.x, gv.y, gv.z, gv.w };
    float be[4] = { bv.x, bv.y, bv.z, bv.w };

    float ov[4];
#pragma unroll
    for (int j = 0; j < 4; j++) {
        float t = (v[j] - mean) * rstd * ga[j] + be[j];
        if (relu) t = fmaxf(t, 0.f);
        ov[j] = t;
    }
    *(float4*)&out[(size_t)row * DD + tid * 4] = *(float4*)ov;
}

// ---------------- launch ------------------------------------------------------
extern "C" void kernel_launch(void* const* d_in, const int* in_sizes, int n_in,
                              void* d_out, int out_size)
{
    (void)in_sizes; (void)n_in; (void)out_size;

    const int*   x    = (const int*)  d_in[0];
    const float* emb  = (const float*)d_in[1];
    const float* WfQ  = (const float*)d_in[2];
    const float* bfQ  = (const float*)d_in[3];
    const float* WfK  = (const float*)d_in[4];
    const float* bfK  = (const float*)d_in[5];
    const float* WfV  = (const float*)d_in[6];
    const float* bfV  = (const float*)d_in[7];
    const float* WQ   = (const float*)d_in[8];
    const float* bQ   = (const float*)d_in[9];
    const float* WK   = (const float*)d_in[10];
    const float* bK   = (const float*)d_in[11];
    const float* WV   = (const float*)d_in[12];
    const float* bV   = (const float*)d_in[13];
    const float* Wo   = (const float*)d_in[14];
    const float* bo   = (const float*)d_in[15];
    const float* W1   = (const float*)d_in[16];
    const float* b1   = (const float*)d_in[17];
    const float* W2   = (const float*)d_in[18];
    const float* b2   = (const float*)d_in[19];
    const float* gamma= (const float*)d_in[20];
    const float* beta = (const float*)d_in[21];
    float* out = (float*)d_out;

    float* base = nullptr;
    cudaGetSymbolAddress((void**)&base, g_scratch);

    float* Z   = base + 0 * (size_t)NT;
    float* Qb  = base + 1 * (size_t)NT;
    float* Kb  = base + 2 * (size_t)NT;
    float* Vb  = base + 3 * (size_t)NT;
    float* QH  = base + 4 * (size_t)NT;
    float* KH  = base + 5 * (size_t)NT;
    float* VH  = base + 6 * (size_t)NT;
    float* ATT = base + 7 * (size_t)NT;
    float* AO  = base + 8 * (size_t)NT;
    float* Aa  = base + 9 * (size_t)NT;
    float* H1  = base + 10 * (size_t)NT;   // 8192 x 2048
    float* F   = base + 14 * (size_t)NT;
    float* WQr = base + 15 * (size_t)NT;
    float* WKr = WQr + DD * DD;
    float* WVr = WKr + DD * DD;

    cudaFuncSetAttribute(attention_kernel,
                         cudaFuncAttributeMaxDynamicSharedMemorySize, ATT_SMEM);

    // 1. embedding + PE
    embed_pe_kernel<<<NT / 256, 256>>>(x, emb, Z);

    // 2. repack per-head weights
    repack_kernel<<<DD * DD / 256, 256>>>(WQ, WQr);
    repack_kernel<<<DD * DD / 256, 256>>>(WK, WKr);
    repack_kernel<<<DD * DD / 256, 256>>>(WV, WVr);

    dim3 g512(DD / 128, NTOK / 128);     // (4, 64)
    dim3 gff(DFF / 128, NTOK / 128);     // (16, 64)

    // 3. fused QKV projections
    gemm_bias_kernel<<<g512, 256>>>(NTOK, DD, DD, Z, WfQ, bfQ, Qb, 0);
    gemm_bias_kernel<<<g512, 256>>>(NTOK, DD, DD, Z, WfK, bfK, Kb, 0);
    gemm_bias_kernel<<<g512, 256>>>(NTOK, DD, DD, Z, WfV, bfV, Vb, 0);

    // 4. per-head projections (repacked to single 512x512 GEMMs)
    gemm_bias_kernel<<<g512, 256>>>(NTOK, DD, DD, Qb, WQr, bQ, QH, 0);
    gemm_bias_kernel<<<g512, 256>>>(NTOK, DD, DD, Kb, WKr, bK, KH, 0);
    gemm_bias_kernel<<<g512, 256>>>(NTOK, DD, DD, Vb, WVr, bV, VH, 0);

    // 5. attention (flash, fused softmax), writes concat layout directly
    attention_kernel<<<dim3(SS / 64, BB * HH), 256, ATT_SMEM>>>(QH, KH, VH, ATT);

    // 6. output projection + residual LN
    gemm_bias_kernel<<<g512, 256>>>(NTOK, DD, DD, ATT, Wo, bo, AO, 0);
    add_ln_kernel<<<NTOK, 128>>>(AO, Z, gamma, beta, Aa, 0);

    // 7. FFN
    gemm_bias_kernel<<<gff, 256>>>(NTOK, DFF, DD, Aa, W1, b1, H1, 1);
    gemm_bias_kernel<<<g512, 256>>>(NTOK, DD, DFF, H1, W2, b2, F, 0);

    // 8. residual LN + final relu -> output
    add_ln_kernel<<<NTOK, 128>>>(F, Aa, gamma, beta, out, 1);
}

// round 2
// speedup vs baseline: 2.6488x; 2.6488x over previous
#include <cuda_runtime.h>
#include <math.h>
#include <stdint.h>

// ---------------- problem constants ----------------
#define BB 4
#define SS 2048
#define DD 512
#define HH 8
#define DHEAD 64
#define DFF 2048
#define NTOK (BB*SS)          // 8192 tokens
#define NT (NTOK*DD)          // 4194304 floats per [tokens, 512] buffer

// ---------------- scratch ----------------
__device__ float g_scratch[15*(size_t)NT + 3*DD*DD];

// ---------------- helpers ----------------
__device__ __forceinline__ uint32_t f2tf(float x) {
    uint32_t u;
    asm("cvt.rna.tf32.f32 %0, %1;" : "=r"(u) : "f"(x));
    return u;
}

#define MMA_TF32(d, a0, a1, a2, a3, b0, b1)                                \
    asm volatile("mma.sync.aligned.m16n8k8.row.col.f32.tf32.tf32.f32 "     \
        "{%0,%1,%2,%3}, {%4,%5,%6,%7}, {%8,%9}, {%0,%1,%2,%3};"            \
        : "+f"(d[0]), "+f"(d[1]), "+f"(d[2]), "+f"(d[3])                   \
        : "r"(a0), "r"(a1), "r"(a2), "r"(a3), "r"(b0), "r"(b1))

// ---------------- embedding + sinusoidal PE ----------------
__global__ void embed_pe_kernel(const int* __restrict__ x, const float* __restrict__ emb,
                                float* __restrict__ z)
{
    int idx = blockIdx.x * blockDim.x + threadIdx.x;
    if (idx >= NT) return;
    int d = idx & (DD - 1);
    int t = idx >> 9;
    int s = t & (SS - 1);
    float di = (float)d * (1.0f / (float)DD);
    float ang = (float)s / powf(10000.0f, di);
    float pe = (d & 1) ? cosf(ang) : sinf(ang);
    z[idx] = emb[(size_t)x[t] * DD + d] + pe;
}

// ---------------- repack per-head weight [H,512,64] -> [512, H*64] ----------
__global__ void repack_kernel(const float* __restrict__ W, float* __restrict__ Wr)
{
    int idx = blockIdx.x * blockDim.x + threadIdx.x;
    if (idx >= DD * DD) return;
    int n = idx & (DD - 1);
    int d = idx >> 9;
    int h = n >> 6, k = n & 63;
    Wr[idx] = W[((size_t)h * DD + d) * DHEAD + k];
}

// ---------------- tf32 tensor-core GEMM: C = A[M,K] @ W[K,N] + bias (+relu) --
// 128x128 tile, BK=16, 256 threads (8 warps as 2m x 4n), warp tile 64x32.
#define GS_A 20    // As[m][k] row stride (16 + 4) — conflict-free quad reads
#define GS_B 136   // Bs[k][n] row stride (128 + 8)

__global__ __launch_bounds__(256, 2) void gemm_tf32_kernel(
    int M, int N, int K,
    const float* __restrict__ A, const float* __restrict__ W,
    const float* __restrict__ bias, float* __restrict__ C, int relu)
{
    __shared__ uint32_t As[128 * GS_A];
    __shared__ uint32_t Bs[16 * GS_B];

    const int tid  = threadIdx.x;
    const int warp = tid >> 5;
    const int lane = tid & 31;
    const int qr   = lane >> 2;
    const int qc   = lane & 3;
    const int wm   = warp & 1;       // 0..1
    const int wn   = warp >> 1;      // 0..3
    const int m0   = blockIdx.y * 128;
    const int n0   = blockIdx.x * 128;

    float acc[4][4][4];
#pragma unroll
    for (int i = 0; i < 4; i++)
#pragma unroll
        for (int j = 0; j < 4; j++)
#pragma unroll
            for (int c = 0; c < 4; c++) acc[i][j][c] = 0.f;

    // staging registers
    float4 ar[2], br[2];
    // A: 128x16 tile -> 512 float4, 2 per thread. B: 16x128 -> 512 float4.
#pragma unroll
    for (int p = 0; p < 2; p++) {
        int idx = p * 256 + tid;
        int arow = idx >> 2, ac = (idx & 3) * 4;
        ar[p] = *(const float4*)&A[(size_t)(m0 + arow) * K + ac];
        int krow = idx >> 5, nc = (idx & 31) * 4;
        br[p] = *(const float4*)&W[(size_t)krow * N + n0 + nc];
    }

    for (int k0 = 0; k0 < K; k0 += 16) {
        __syncthreads();
#pragma unroll
        for (int p = 0; p < 2; p++) {
            int idx = p * 256 + tid;
            int arow = idx >> 2, ac = (idx & 3) * 4;
            As[arow * GS_A + ac + 0] = f2tf(ar[p].x);
            As[arow * GS_A + ac + 1] = f2tf(ar[p].y);
            As[arow * GS_A + ac + 2] = f2tf(ar[p].z);
            As[arow * GS_A + ac + 3] = f2tf(ar[p].w);
            int krow = idx >> 5, nc = (idx & 31) * 4;
            Bs[krow * GS_B + nc + 0] = f2tf(br[p].x);
            Bs[krow * GS_B + nc + 1] = f2tf(br[p].y);
            Bs[krow * GS_B + nc + 2] = f2tf(br[p].z);
            Bs[krow * GS_B + nc + 3] = f2tf(br[p].w);
        }
        __syncthreads();

        if (k0 + 16 < K) {
#pragma unroll
            for (int p = 0; p < 2; p++) {
                int idx = p * 256 + tid;
                int arow = idx >> 2, ac = (idx & 3) * 4;
                ar[p] = *(const float4*)&A[(size_t)(m0 + arow) * K + k0 + 16 + ac];
                int krow = idx >> 5, nc = (idx & 31) * 4;
                br[p] = *(const float4*)&W[(size_t)(k0 + 16 + krow) * N + n0 + nc];
            }
        }

#pragma unroll
        for (int kk = 0; kk < 16; kk += 8) {
            uint32_t af[4][4], bf[4][2];
#pragma unroll
            for (int mt = 0; mt < 4; mt++) {
                int mrow = wm * 64 + mt * 16 + qr;
                af[mt][0] = As[mrow * GS_A + kk + qc];
                af[mt][1] = As[(mrow + 8) * GS_A + kk + qc];
                af[mt][2] = As[mrow * GS_A + kk + qc + 4];
                af[mt][3] = As[(mrow + 8) * GS_A + kk + qc + 4];
            }
#pragma unroll
            for (int nt = 0; nt < 4; nt++) {
                int ncol = wn * 32 + nt * 8 + qr;
                bf[nt][0] = Bs[(kk + qc) * GS_B + ncol];
                bf[nt][1] = Bs[(kk + qc + 4) * GS_B + ncol];
            }
#pragma unroll
            for (int mt = 0; mt < 4; mt++)
#pragma unroll
                for (int nt = 0; nt < 4; nt++)
                    MMA_TF32(acc[mt][nt], af[mt][0], af[mt][1], af[mt][2], af[mt][3],
                             bf[nt][0], bf[nt][1]);
        }
    }

    // epilogue
#pragma unroll
    for (int mt = 0; mt < 4; mt++) {
        int row = m0 + wm * 64 + mt * 16 + qr;
#pragma unroll
        for (int nt = 0; nt < 4; nt++) {
            int col = n0 + wn * 32 + nt * 8 + qc * 2;
            float2 bv = *(const float2*)&bias[col];
            float2 v0, v1;
            v0.x = acc[mt][nt][0] + bv.x;
            v0.y = acc[mt][nt][1] + bv.y;
            v1.x = acc[mt][nt][2] + bv.x;
            v1.y = acc[mt][nt][3] + bv.y;
            if (relu) {
                v0.x = fmaxf(v0.x, 0.f); v0.y = fmaxf(v0.y, 0.f);
                v1.x = fmaxf(v1.x, 0.f); v1.y = fmaxf(v1.y, 0.f);
            }
            *(float2*)&C[(size_t)row * N + col] = v0;
            *(float2*)&C[(size_t)(row + 8) * N + col] = v1;
        }
    }
}

// ---------------- flash attention with tf32 mma ------------------------------
// CTA: 256 threads (8 warps), 128 q rows, 64-wide KV tiles. Warp w owns q rows
// [w*16, w*16+16). Q frags live in registers (pre-scaled by 1/8).
#define AKS 68     // Ks[s][k] row stride
#define AVS 72     // Vs[s][v] row stride
#define APS 68     // Ps/Q-staging [row][*] stride
#define ATT_SMEM ((64*AKS + 64*AVS + 128*APS) * (int)sizeof(uint32_t))

__global__ __launch_bounds__(256, 1) void attention_kernel(
    const float* __restrict__ Qh, const float* __restrict__ Kh,
    const float* __restrict__ Vh, float* __restrict__ Out)
{
    extern __shared__ uint32_t sm[];
    uint32_t* Ks = sm;
    uint32_t* Vs = Ks + 64 * AKS;
    uint32_t* Ps = Vs + 64 * AVS;   // also Q staging

    const int tid  = threadIdx.x;
    const int w    = tid >> 5;
    const int lane = tid & 31;
    const int qr   = lane >> 2;
    const int qc   = lane & 3;
    const int q0   = blockIdx.x * 128;
    const int bh   = blockIdx.y;
    const int rb   = (bh >> 3) * SS;
    const int cq   = (bh & 7) * DHEAD;

    // stage Q (scaled, tf32) coalesced into Ps region
#pragma unroll
    for (int it = 0; it < 32; ++it) {
        int idx = it * 256 + tid;
        int r = idx >> 6, k = idx & 63;
        Ps[r * APS + k] = f2tf(Qh[(size_t)(rb + q0 + r) * DD + cq + k] * 0.125f);
    }
    __syncthreads();

    uint32_t qf[8][4];
    {
        int base0 = (w * 16 + qr) * APS;
        int base1 = (w * 16 + qr + 8) * APS;
#pragma unroll
        for (int ks = 0; ks < 8; ks++) {
            int kk = ks * 8;
            qf[ks][0] = Ps[base0 + kk + qc];
            qf[ks][1] = Ps[base1 + kk + qc];
            qf[ks][2] = Ps[base0 + kk + qc + 4];
            qf[ks][3] = Ps[base1 + kk + qc + 4];
        }
    }

    float m[2] = { -1e30f, -1e30f };
    float l[2] = { 0.f, 0.f };
    float o[8][4];
#pragma unroll
    for (int i = 0; i < 8; i++)
#pragma unroll
        for (int c = 0; c < 4; c++) o[i][c] = 0.f;

    const int prow0 = (w * 16 + qr) * APS;
    const int prow1 = (w * 16 + qr + 8) * APS;

    for (int s0 = 0; s0 < SS; s0 += 64) {
        __syncthreads();   // Ps/Ks/Vs free (also covers Q-frag reads on iter 0)
#pragma unroll
        for (int it = 0; it < 16; ++it) {
            int idx = it * 256 + tid;
            int r = idx >> 6, k = idx & 63;
            Ks[r * AKS + k] = f2tf(Kh[(size_t)(rb + s0 + r) * DD + cq + k]);
            Vs[r * AVS + k] = f2tf(Vh[(size_t)(rb + s0 + r) * DD + cq + k]);
        }
        __syncthreads();

        // S = Q K^T (scaled)
        float s[8][4];
#pragma unroll
        for (int nt = 0; nt < 8; nt++)
#pragma unroll
            for (int c = 0; c < 4; c++) s[nt][c] = 0.f;

#pragma unroll
        for (int ks = 0; ks < 8; ks++) {
            int kk = ks * 8;
#pragma unroll
            for (int nt = 0; nt < 8; nt++) {
                uint32_t b0 = Ks[(nt * 8 + qr) * AKS + kk + qc];
                uint32_t b1 = Ks[(nt * 8 + qr) * AKS + kk + qc + 4];
                MMA_TF32(s[nt], qf[ks][0], qf[ks][1], qf[ks][2], qf[ks][3], b0, b1);
            }
        }

        // online softmax (two rows per thread: qr -> c0,c1 ; qr+8 -> c2,c3)
        float rmax0 = -1e30f, rmax1 = -1e30f;
#pragma unroll
        for (int nt = 0; nt < 8; nt++) {
            rmax0 = fmaxf(rmax0, fmaxf(s[nt][0], s[nt][1]));
            rmax1 = fmaxf(rmax1, fmaxf(s[nt][2], s[nt][3]));
        }
        rmax0 = fmaxf(rmax0, __shfl_xor_sync(0xffffffffu, rmax0, 1));
        rmax0 = fmaxf(rmax0, __shfl_xor_sync(0xffffffffu, rmax0, 2));
        rmax1 = fmaxf(rmax1, __shfl_xor_sync(0xffffffffu, rmax1, 1));
        rmax1 = fmaxf(rmax1, __shfl_xor_sync(0xffffffffu, rmax1, 2));

        float mn0 = fmaxf(m[0], rmax0);
        float mn1 = fmaxf(m[1], rmax1);
        float alpha0 = __expf(m[0] - mn0);
        float alpha1 = __expf(m[1] - mn1);

        float rs0 = 0.f, rs1 = 0.f;
#pragma unroll
        for (int nt = 0; nt < 8; nt++) {
            float p0 = __expf(s[nt][0] - mn0);
            float p1 = __expf(s[nt][1] - mn0);
            float p2 = __expf(s[nt][2] - mn1);
            float p3 = __expf(s[nt][3] - mn1);
            s[nt][0] = p0; s[nt][1] = p1; s[nt][2] = p2; s[nt][3] = p3;
            rs0 += p0 + p1;
            rs1 += p2 + p3;
        }
        rs0 += __shfl_xor_sync(0xffffffffu, rs0, 1);
        rs0 += __shfl_xor_sync(0xffffffffu, rs0, 2);
        rs1 += __shfl_xor_sync(0xffffffffu, rs1, 1);
        rs1 += __shfl_xor_sync(0xffffffffu, rs1, 2);

        l[0] = l[0] * alpha0 + rs0;
        l[1] = l[1] * alpha1 + rs1;
        m[0] = mn0; m[1] = mn1;
#pragma unroll
        for (int nt = 0; nt < 8; nt++) {
            o[nt][0] *= alpha0; o[nt][1] *= alpha0;
            o[nt][2] *= alpha1; o[nt][3] *= alpha1;
        }

        // store P (tf32) to smem
#pragma unroll
        for (int nt = 0; nt < 8; nt++) {
            int col = nt * 8 + 2 * qc;
            Ps[prow0 + col]     = f2tf(s[nt][0]);
            Ps[prow0 + col + 1] = f2tf(s[nt][1]);
            Ps[prow1 + col]     = f2tf(s[nt][2]);
            Ps[prow1 + col + 1] = f2tf(s[nt][3]);
        }
        __syncthreads();

        // O += P V
#pragma unroll
        for (int ks = 0; ks < 8; ks++) {
            int kk = ks * 8;
            uint32_t a0 = Ps[prow0 + kk + qc];
            uint32_t a1 = Ps[prow1 + kk + qc];
            uint32_t a2 = Ps[prow0 + kk + qc + 4];
            uint32_t a3 = Ps[prow1 + kk + qc + 4];
#pragma unroll
            for (int vt = 0; vt < 8; vt++) {
                uint32_t b0 = Vs[(kk + qc) * AVS + vt * 8 + qr];
                uint32_t b1 = Vs[(kk + qc + 4) * AVS + vt * 8 + qr];
                MMA_TF32(o[vt], a0, a1, a2, a3, b0, b1);
            }
        }
    }

    // epilogue
    float inv0 = 1.f / l[0];
    float inv1 = 1.f / l[1];
    int row = rb + q0 + w * 16 + qr;
#pragma unroll
    for (int vt = 0; vt < 8; vt++) {
        int col = cq + vt * 8 + 2 * qc;
        float2 v0, v1;
        v0.x = o[vt][0] * inv0; v0.y = o[vt][1] * inv0;
        v1.x = o[vt][2] * inv1; v1.y = o[vt][3] * inv1;
        *(float2*)&Out[(size_t)row * DD + col] = v0;
        *(float2*)&Out[(size_t)(row + 8) * DD + col] = v1;
    }
}

// ---------------- fused residual + LayerNorm (+relu) -------------------------
__global__ __launch_bounds__(128) void add_ln_kernel(
    const float* __restrict__ X, const float* __restrict__ R,
    const float* __restrict__ gamma, const float* __restrict__ beta,
    float* __restrict__ out, int relu)
{
    const int row = blockIdx.x;
    const int tid = threadIdx.x;

    float4 xv = *(const float4*)&X[(size_t)row * DD + tid * 4];
    float4 rv = *(const float4*)&R[(size_t)row * DD + tid * 4];
    float v[4] = { xv.x + rv.x, xv.y + rv.y, xv.z + rv.z, xv.w + rv.w };

    float s = v[0] + v[1] + v[2] + v[3];
    float sq = v[0] * v[0] + v[1] * v[1] + v[2] * v[2] + v[3] * v[3];
#pragma unroll
    for (int off = 16; off >= 1; off >>= 1) {
        s += __shfl_xor_sync(0xffffffffu, s, off);
        sq += __shfl_xor_sync(0xffffffffu, sq, off);
    }
    __shared__ float sw[4], sqw[4];
    int w = tid >> 5;
    if ((tid & 31) == 0) { sw[w] = s; sqw[w] = sq; }
    __syncthreads();
    s = sw[0] + sw[1] + sw[2] + sw[3];
    sq = sqw[0] + sqw[1] + sqw[2] + sqw[3];

    float mean = s * (1.0f / (float)DD);
    float var = sq * (1.0f / (float)DD) - mean * mean;
    float rstd = rsqrtf(var + 1e-5f);

    float4 gv = *(const float4*)&gamma[tid * 4];
    float4 bv = *(const float4*)&beta[tid * 4];
    float ga[4] = { gv.x, gv.y, gv.z, gv.w };
    float be[4] = { bv.x, bv.y, bv.z, bv.w };

    float ov[4];
#pragma unroll
    for (int j = 0; j < 4; j++) {
        float t = (v[j] - mean) * rstd * ga[j] + be[j];
        if (relu) t = fmaxf(t, 0.f);
        ov[j] = t;
    }
    *(float4*)&out[(size_t)row * DD + tid * 4] = *(float4*)ov;
}

// ---------------- launch ------------------------------------------------------
extern "C" void kernel_launch(void* const* d_in, const int* in_sizes, int n_in,
                              void* d_out, int out_size)
{
    (void)in_sizes; (void)n_in; (void)out_size;

    const int*   x    = (const int*)  d_in[0];
    const float* emb  = (const float*)d_in[1];
    const float* WfQ  = (const float*)d_in[2];
    const float* bfQ  = (const float*)d_in[3];
    const float* WfK  = (const float*)d_in[4];
    const float* bfK  = (const float*)d_in[5];
    const float* WfV  = (const float*)d_in[6];
    const float* bfV  = (const float*)d_in[7];
    const float* WQ   = (const float*)d_in[8];
    const float* bQ   = (const float*)d_in[9];
    const float* WK   = (const float*)d_in[10];
    const float* bK   = (const float*)d_in[11];
    const float* WV   = (const float*)d_in[12];
    const float* bV   = (const float*)d_in[13];
    const float* Wo   = (const float*)d_in[14];
    const float* bo   = (const float*)d_in[15];
    const float* W1   = (const float*)d_in[16];
    const float* b1   = (const float*)d_in[17];
    const float* W2   = (const float*)d_in[18];
    const float* b2   = (const float*)d_in[19];
    const float* gamma= (const float*)d_in[20];
    const float* beta = (const float*)d_in[21];
    float* out = (float*)d_out;

    float* base = nullptr;
    cudaGetSymbolAddress((void**)&base, g_scratch);

    float* Z   = base + 0 * (size_t)NT;
    float* Qb  = base + 1 * (size_t)NT;
    float* Kb  = base + 2 * (size_t)NT;
    float* Vb  = base + 3 * (size_t)NT;
    float* QH  = base + 4 * (size_t)NT;
    float* KH  = base + 5 * (size_t)NT;
    float* VH  = base + 6 * (size_t)NT;
    float* ATT = base + 7 * (size_t)NT;
    float* AO  = base + 8 * (size_t)NT;
    float* Aa  = base + 9 * (size_t)NT;
    float* H1  = base + 10 * (size_t)NT;   // 8192 x 2048
    float* F   = base + 14 * (size_t)NT;
    float* WQr = base + 15 * (size_t)NT;
    float* WKr = WQr + DD * DD;
    float* WVr = WKr + DD * DD;

    cudaFuncSetAttribute(attention_kernel,
                         cudaFuncAttributeMaxDynamicSharedMemorySize, ATT_SMEM);

    // 1. embedding + PE
    embed_pe_kernel<<<NT / 256, 256>>>(x, emb, Z);

    // 2. repack per-head weights
    repack_kernel<<<DD * DD / 256, 256>>>(WQ, WQr);
    repack_kernel<<<DD * DD / 256, 256>>>(WK, WKr);
    repack_kernel<<<DD * DD / 256, 256>>>(WV, WVr);

    dim3 g512(DD / 128, NTOK / 128);     // (4, 64)
    dim3 gff(DFF / 128, NTOK / 128);     // (16, 64)

    // 3. fused QKV projections
    gemm_tf32_kernel<<<g512, 256>>>(NTOK, DD, DD, Z, WfQ, bfQ, Qb, 0);
    gemm_tf32_kernel<<<g512, 256>>>(NTOK, DD, DD, Z, WfK, bfK, Kb, 0);
    gemm_tf32_kernel<<<g512, 256>>>(NTOK, DD, DD, Z, WfV, bfV, Vb, 0);

    // 4. per-head projections (repacked to single 512x512 GEMMs)
    gemm_tf32_kernel<<<g512, 256>>>(NTOK, DD, DD, Qb, WQr, bQ, QH, 0);
    gemm_tf32_kernel<<<g512, 256>>>(NTOK, DD, DD, Kb, WKr, bK, KH, 0);
    gemm_tf32_kernel<<<g512, 256>>>(NTOK, DD, DD, Vb, WVr, bV, VH, 0);

    // 5. attention (flash, tf32 mma), writes concat layout directly
    attention_kernel<<<dim3(SS / 128, BB * HH), 256, ATT_SMEM>>>(QH, KH, VH, ATT);

    // 6. output projection + residual LN
    gemm_tf32_kernel<<<g512, 256>>>(NTOK, DD, DD, ATT, Wo, bo, AO, 0);
    add_ln_kernel<<<NTOK, 128>>>(AO, Z, gamma, beta, Aa, 0);

    // 7. FFN
    gemm_tf32_kernel<<<gff, 256>>>(NTOK, DFF, DD, Aa, W1, b1, H1, 1);
    gemm_tf32_kernel<<<g512, 256>>>(NTOK, DD, DFF, H1, W2, b2, F, 0);

    // 8. residual LN + final relu -> output
    add_ln_kernel<<<NTOK, 128>>>(F, Aa, gamma, beta, out, 1);
}